// round 3
// baseline (speedup 1.0000x reference)
#include <cuda_runtime.h>
#include <cuda_bf16.h>

#define NUM_B 512
#define NUM_P 196          // 14*14 patch locations
#define NTOT  (NUM_B * NUM_P)   // 100352 = 392 * 256

__device__ float g_mean[NUM_P];
__device__ float g_inv[NUM_P];   // pi / (std + 1e-8)

// ---------------------------------------------------------------------------
// Kernel 1: per-patch-location mean / inv-std over B*4 = 2048 values (ddof=1)
// ---------------------------------------------------------------------------
__global__ void qf_stats_kernel(const float* __restrict__ x) {
    const int p = blockIdx.x;           // 0..195
    const int r = p / 14, c = p % 14;
    const float* base = x + (2 * r) * 28 + 2 * c;

    float s = 0.f, q = 0.f;
    for (int b = threadIdx.x; b < NUM_B; b += blockDim.x) {
        const float* xb = base + b * 784;
        float v0 = xb[0], v1 = xb[1], v2 = xb[28], v3 = xb[29];
        s += (v0 + v1) + (v2 + v3);
        q += v0 * v0 + v1 * v1 + v2 * v2 + v3 * v3;
    }

    // block reduction (256 threads = 8 warps)
    __shared__ float sh_s[8], sh_q[8];
    const int lane = threadIdx.x & 31, wid = threadIdx.x >> 5;
#pragma unroll
    for (int o = 16; o > 0; o >>= 1) {
        s += __shfl_down_sync(0xffffffffu, s, o);
        q += __shfl_down_sync(0xffffffffu, q, o);
    }
    if (lane == 0) { sh_s[wid] = s; sh_q[wid] = q; }
    __syncthreads();
    if (wid == 0) {
        s = (lane < 8) ? sh_s[lane] : 0.f;
        q = (lane < 8) ? sh_q[lane] : 0.f;
#pragma unroll
        for (int o = 4; o > 0; o >>= 1) {
            s += __shfl_down_sync(0xffffffffu, s, o);
            q += __shfl_down_sync(0xffffffffu, q, o);
        }
        if (lane == 0) {
            const float n = 2048.0f;
            float mean = s / n;
            float var  = fmaxf((q - s * mean) / (n - 1.0f), 0.0f);
            g_mean[p] = mean;
            g_inv[p]  = 3.14159265358979323846f / (sqrtf(var) + 1e-8f);
        }
    }
}

// ---------------------------------------------------------------------------
// Circuit helpers (16-amplitude state in registers, fully unrolled)
// wire w <-> bitmask (8 >> w)
// ---------------------------------------------------------------------------
template <int M>
__device__ __forceinline__ void ry_real(float* a, float c, float s) {
#pragma unroll
    for (int i = 0; i < 16; i++)
        if (!(i & M)) {
            const int j = i | M;
            float a0 = a[i], a1 = a[j];
            a[i] = c * a0 - s * a1;
            a[j] = s * a0 + c * a1;
        }
}

template <int M>
__device__ __forceinline__ void ry_cplx(float* ar, float* ai, float c, float s) {
#pragma unroll
    for (int i = 0; i < 16; i++)
        if (!(i & M)) {
            const int j = i | M;
            float r0 = ar[i], r1 = ar[j];
            ar[i] = c * r0 - s * r1;
            ar[j] = s * r0 + c * r1;
            float i0 = ai[i], i1 = ai[j];
            ai[i] = c * i0 - s * i1;
            ai[j] = s * i0 + c * i1;
        }
}

template <int MC, int MT>
__device__ __forceinline__ void cnot_real(float* a) {
#pragma unroll
    for (int i = 0; i < 16; i++)
        if ((i & MC) && !(i & MT)) {
            const int j = i | MT;
            float t = a[i]; a[i] = a[j]; a[j] = t;
        }
}

template <int MC, int MT>
__device__ __forceinline__ void cnot_cplx(float* ar, float* ai) {
    cnot_real<MC, MT>(ar);
    cnot_real<MC, MT>(ai);
}

// ---------------------------------------------------------------------------
// Kernel 2: one 4-qubit circuit per thread.
// ---------------------------------------------------------------------------
__global__ void __launch_bounds__(256)
qf_circuit_kernel(const float* __restrict__ x,
                  const float* __restrict__ params,
                  float* __restrict__ out) {
    // --- per-block parameter precompute (params-only quantities) ---
    // sC/sS: [layer][col (0|1)][wire] cos/sin of params/2 for the RY columns
    // sPr/sPi: the 16 complex phasors of the layer-0 RZ product
    __shared__ float sC[2][2][4], sS[2][2][4];
    __shared__ float sPr[16], sPi[16];
    if (threadIdx.x == 0) {
        float cz[4], sz[4];
#pragma unroll
        for (int l = 0; l < 2; l++)
#pragma unroll
            for (int i = 0; i < 4; i++) {
                float s_, c_;
                __sincosf(0.5f * params[l * 12 + i * 3 + 0], &s_, &c_);
                sC[l][0][i] = c_; sS[l][0][i] = s_;
                __sincosf(0.5f * params[l * 12 + i * 3 + 1], &s_, &c_);
                sC[l][1][i] = c_; sS[l][1][i] = s_;
            }
#pragma unroll
        for (int i = 0; i < 4; i++)
            __sincosf(0.5f * params[i * 3 + 2], &sz[i], &cz[i]);
        // phasor(idx) = prod_w exp(-i*theta_w/2 * (bit0 ? +1... ) ):
        // bit clear -> (cz, -sz); bit set -> (cz, +sz)
#pragma unroll
        for (int idx = 0; idx < 16; idx++) {
            float pr = 1.f, pim = 0.f;
#pragma unroll
            for (int w = 0; w < 4; w++) {
                float swv = (idx & (8 >> w)) ? sz[w] : -sz[w];
                float nr = pr * cz[w] - pim * swv;
                pim = pr * swv + pim * cz[w];
                pr = nr;
            }
            sPr[idx] = pr; sPi[idx] = pim;
        }
    }
    __syncthreads();

    const int tid = blockIdx.x * 256 + threadIdx.x;   // exactly NTOT threads
    const int b = tid / NUM_P;
    const int p = tid - b * NUM_P;
    const int r = p / 14, c = p - r * 14;

    // gather the 2x2 patch
    const float* xb = x + b * 784 + (2 * r) * 28 + 2 * c;
    float v0 = xb[0], v1 = xb[1], v2 = xb[28], v3 = xb[29];
    const float m = g_mean[p], inv = g_inv[p];
    float ang[4] = { (v0 - m) * inv, (v1 - m) * inv, (v2 - m) * inv, (v3 - m) * inv };

    // initial product state (after the 4 input RYs)
    float cw[4], sw[4];
#pragma unroll
    for (int w = 0; w < 4; w++) __sincosf(0.5f * ang[w], &sw[w], &cw[w]);

    float ar[16], ai[16];
#pragma unroll
    for (int idx = 0; idx < 16; idx++) {
        float f0 = (idx & 8) ? sw[0] : cw[0];
        float f1 = (idx & 4) ? sw[1] : cw[1];
        float f2 = (idx & 2) ? sw[2] : cw[2];
        float f3 = (idx & 1) ? sw[3] : cw[3];
        ar[idx] = (f0 * f1) * (f2 * f3);
    }

    // ---- layer 0 (state stays real until RZ) ----
    ry_real<8>(ar, sC[0][0][0], sS[0][0][0]);
    ry_real<4>(ar, sC[0][0][1], sS[0][0][1]);
    ry_real<2>(ar, sC[0][0][2], sS[0][0][2]);
    ry_real<1>(ar, sC[0][0][3], sS[0][0][3]);
    cnot_real<8, 4>(ar); cnot_real<4, 2>(ar); cnot_real<2, 1>(ar);
    ry_real<8>(ar, sC[0][1][0], sS[0][1][0]);
    ry_real<4>(ar, sC[0][1][1], sS[0][1][1]);
    ry_real<2>(ar, sC[0][1][2], sS[0][1][2]);
    ry_real<1>(ar, sC[0][1][3], sS[0][1][3]);
    cnot_real<4, 8>(ar); cnot_real<2, 4>(ar); cnot_real<1, 2>(ar);
    // layer-0 RZ: multiply by precomputed phasors
#pragma unroll
    for (int idx = 0; idx < 16; idx++) {
        ai[idx] = ar[idx] * sPi[idx];
        ar[idx] = ar[idx] * sPr[idx];
    }

    // ---- layer 1 (complex; final RZ skipped — pure phases don't change probs) ----
    ry_cplx<8>(ar, ai, sC[1][0][0], sS[1][0][0]);
    ry_cplx<4>(ar, ai, sC[1][0][1], sS[1][0][1]);
    ry_cplx<2>(ar, ai, sC[1][0][2], sS[1][0][2]);
    ry_cplx<1>(ar, ai, sC[1][0][3], sS[1][0][3]);
    cnot_cplx<8, 4>(ar, ai); cnot_cplx<4, 2>(ar, ai); cnot_cplx<2, 1>(ar, ai);
    ry_cplx<8>(ar, ai, sC[1][1][0], sS[1][1][0]);
    ry_cplx<4>(ar, ai, sC[1][1][1], sS[1][1][1]);
    ry_cplx<2>(ar, ai, sC[1][1][2], sS[1][1][2]);
    ry_cplx<1>(ar, ai, sC[1][1][3], sS[1][1][3]);
    cnot_cplx<4, 8>(ar, ai); cnot_cplx<2, 4>(ar, ai); cnot_cplx<1, 2>(ar, ai);

    // ---- probabilities and Z expectations ----
    float z0 = 0.f, z1 = 0.f, z2 = 0.f, z3 = 0.f;
#pragma unroll
    for (int idx = 0; idx < 16; idx++) {
        float pv = fmaf(ar[idx], ar[idx], ai[idx] * ai[idx]);
        z0 += (idx & 8) ? -pv : pv;
        z1 += (idx & 4) ? -pv : pv;
        z2 += (idx & 2) ? -pv : pv;
        z3 += (idx & 1) ? -pv : pv;
    }

    float4 zout = make_float4(z0, z1, z2, z3);
    *reinterpret_cast<float4*>(out + b * 784 + p * 4) = zout;
}

// ---------------------------------------------------------------------------
extern "C" void kernel_launch(void* const* d_in, const int* in_sizes, int n_in,
                              void* d_out, int out_size) {
    const float* x = (const float*)d_in[0];
    const float* params = (const float*)d_in[1];
    if (n_in >= 2 && in_sizes[0] == 24) {   // robustness vs input ordering
        x = (const float*)d_in[1];
        params = (const float*)d_in[0];
    }
    float* out = (float*)d_out;

    qf_stats_kernel<<<NUM_P, 256>>>(x);
    qf_circuit_kernel<<<NTOT / 256, 256>>>(x, params, out);
}

// round 5
// speedup vs baseline: 1.0363x; 1.0363x over previous
#include <cuda_runtime.h>
#include <cuda_bf16.h>

#define NUM_B 512
#define NUM_P 196          // 14*14 patch locations

typedef unsigned long long u64;

// ---------------------------------------------------------------------------
// f32x2 packed helpers (sm_103a packed fp32 pipe)
// ---------------------------------------------------------------------------
__device__ __forceinline__ u64 pk(float lo, float hi) {
    u64 r; asm("mov.b64 %0, {%1, %2};" : "=l"(r) : "f"(lo), "f"(hi)); return r;
}
__device__ __forceinline__ void upk(float& lo, float& hi, u64 v) {
    asm("mov.b64 {%0, %1}, %2;" : "=f"(lo), "=f"(hi) : "l"(v));
}
__device__ __forceinline__ u64 mul2(u64 a, u64 b) {
    u64 d; asm("mul.rn.f32x2 %0, %1, %2;" : "=l"(d) : "l"(a), "l"(b)); return d;
}
__device__ __forceinline__ u64 fma2(u64 a, u64 b, u64 c) {
    u64 d; asm("fma.rn.f32x2 %0, %1, %2, %3;" : "=l"(d) : "l"(a), "l"(b), "l"(c)); return d;
}
__device__ __forceinline__ u64 swp(u64 v) { float l, h; upk(l, h, v); return pk(h, l); }
__device__ __forceinline__ void sw2(u64& A, u64& B) { u64 t = A; A = B; B = t; }
// exchange hi lanes of A and B
__device__ __forceinline__ void hix(u64& A, u64& B) {
    float al, ah, bl, bh; upk(al, ah, A); upk(bl, bh, B);
    A = pk(al, bh); B = pk(bl, ah);
}
// packed RY on a pack pair: A' = c*A - s*B ; B' = s*A + c*B
__device__ __forceinline__ void pry(u64& A, u64& B, u64 c2, u64 s2, u64 n2) {
    u64 nA = fma2(n2, B, mul2(c2, A));
    u64 nB = fma2(s2, A, mul2(c2, B));
    A = nA; B = nB;
}

// real state: 8 packs, lane = wire3 bit; pack-index bits {4,2,1} = wires {0,1,2}
template <int M>
__device__ __forceinline__ void pryR(u64* R, u64 c2, u64 s2, u64 n2) {
#pragma unroll
    for (int k = 0; k < 8; k++)
        if (!(k & M)) pry(R[k], R[k | M], c2, s2, n2);
}
// complex state: 16 packs (ar, ai); idx bits {8,4,2,1} = wires {0,1,2,3}
template <int M>
__device__ __forceinline__ void pryP(u64* P, u64 c2, u64 s2, u64 n2) {
#pragma unroll
    for (int i = 0; i < 16; i++)
        if (!(i & M)) pry(P[i], P[i | M], c2, s2, n2);
}
template <int MC, int MT>
__device__ __forceinline__ void cnotP(u64* P) {
#pragma unroll
    for (int i = 0; i < 16; i++)
        if ((i & MC) && !(i & MT)) sw2(P[i], P[i | MT]);
}

// ---------------------------------------------------------------------------
// Fused kernel: block = patch location (196 blocks), thread = sample (512).
// Phase A: block-wide stats (mean, pi/(std+1e-8)).  Phase B: circuit/thread.
// ---------------------------------------------------------------------------
__global__ void __launch_bounds__(512, 2)
qf_fused_kernel(const float* __restrict__ x,
                const float* __restrict__ params,
                float* __restrict__ out) {
    __shared__ float sh_s[16], sh_q[16];
    __shared__ float s_stats[2];                  // mean, pi/(std+eps)
    __shared__ u64 sc2[2][2][4], ss2[2][2][4], sn2[2][2][4]; // dup'd cos/sin/-sin
    __shared__ u64 smix[2];                       // layer0 wire3 in-lane (-s,+s)
    __shared__ u64 sPz[16];                       // layer-0 RZ phasor packs

    const int p = blockIdx.x;
    const int r = p / 14, c = p % 14;
    const int b = threadIdx.x;
    const int lane = threadIdx.x & 31, wid = threadIdx.x >> 5;

    // --- load this thread's 2x2 patch ---
    const float* xb = x + b * 784 + (2 * r) * 28 + 2 * c;
    float v0 = xb[0], v1 = xb[1], v2 = xb[28], v3 = xb[29];

    // --- Phase A: stats over the block's 512*4 values ---
    float s = (v0 + v1) + (v2 + v3);
    float q = v0 * v0 + v1 * v1 + v2 * v2 + v3 * v3;
#pragma unroll
    for (int o = 16; o > 0; o >>= 1) {
        s += __shfl_down_sync(0xffffffffu, s, o);
        q += __shfl_down_sync(0xffffffffu, q, o);
    }
    if (lane == 0) { sh_s[wid] = s; sh_q[wid] = q; }
    __syncthreads();

    if (threadIdx.x < 32) {
        float fs = (lane < 16) ? sh_s[lane] : 0.f;
        float fq = (lane < 16) ? sh_q[lane] : 0.f;
#pragma unroll
        for (int o = 8; o > 0; o >>= 1) {
            fs += __shfl_down_sync(0xffffffffu, fs, o);
            fq += __shfl_down_sync(0xffffffffu, fq, o);
        }
        if (lane == 0) {
            const float n = 2048.0f;
            float mean = fs / n;
            float var = fmaxf((fq - fs * mean) / (n - 1.0f), 0.0f);
            s_stats[0] = mean;
            s_stats[1] = 3.14159265358979323846f / (sqrtf(var) + 1e-8f);
        }
    } else if (threadIdx.x == 32) {
        // params-only precompute (overlaps warp0's reduction)
        float cz[4], sz[4];
#pragma unroll
        for (int l = 0; l < 2; l++)
#pragma unroll
            for (int i = 0; i < 4; i++) {
                float s_, c_;
                __sincosf(0.5f * params[l * 12 + i * 3 + 0], &s_, &c_);
                sc2[l][0][i] = pk(c_, c_); ss2[l][0][i] = pk(s_, s_); sn2[l][0][i] = pk(-s_, -s_);
                if (l == 0 && i == 3) smix[0] = pk(-s_, s_);
                __sincosf(0.5f * params[l * 12 + i * 3 + 1], &s_, &c_);
                sc2[l][1][i] = pk(c_, c_); ss2[l][1][i] = pk(s_, s_); sn2[l][1][i] = pk(-s_, -s_);
                if (l == 0 && i == 3) smix[1] = pk(-s_, s_);
            }
#pragma unroll
        for (int i = 0; i < 4; i++)
            __sincosf(0.5f * params[i * 3 + 2], &sz[i], &cz[i]);
#pragma unroll
        for (int idx = 0; idx < 16; idx++) {
            float pr = 1.f, pim = 0.f;
#pragma unroll
            for (int w = 0; w < 4; w++) {
                float swv = (idx & (8 >> w)) ? sz[w] : -sz[w];
                float nr = pr * cz[w] - pim * swv;
                pim = pr * swv + pim * cz[w];
                pr = nr;
            }
            sPz[idx] = pk(pr, pim);
        }
    }
    __syncthreads();

    // --- Phase B: circuit ---
    const float m = s_stats[0], inv = s_stats[1];
    float cw[4], sw[4];
    {
        float a0 = (v0 - m) * inv, a1 = (v1 - m) * inv;
        float a2 = (v2 - m) * inv, a3 = (v3 - m) * inv;
        __sincosf(0.5f * a0, &sw[0], &cw[0]);
        __sincosf(0.5f * a1, &sw[1], &cw[1]);
        __sincosf(0.5f * a2, &sw[2], &cw[2]);
        __sincosf(0.5f * a3, &sw[3], &cw[3]);
    }

    // initial product state after input RYs (real), packed along wire3
    u64 R[8];
    {
        u64 g3 = pk(cw[3], sw[3]);
#pragma unroll
        for (int k = 0; k < 8; k++) {
            float f = ((k & 4) ? sw[0] : cw[0]) * ((k & 2) ? sw[1] : cw[1])
                    * ((k & 1) ? sw[2] : cw[2]);
            R[k] = mul2(pk(f, f), g3);
        }
    }

    // ---- layer 0 (real) ----
    pryR<4>(R, sc2[0][0][0], ss2[0][0][0], sn2[0][0][0]);   // wire0
    pryR<2>(R, sc2[0][0][1], ss2[0][0][1], sn2[0][0][1]);   // wire1
    pryR<1>(R, sc2[0][0][2], ss2[0][0][2], sn2[0][0][2]);   // wire2
    {   // wire3 (lane bit): in-lane packed RY
        u64 c2 = sc2[0][0][3], mx = smix[0];
#pragma unroll
        for (int k = 0; k < 8; k++) R[k] = fma2(c2, R[k], mul2(mx, swp(R[k])));
    }
    // cnot 0->1, 1->2, 2->3
    sw2(R[4], R[6]); sw2(R[5], R[7]);
    sw2(R[2], R[3]); sw2(R[6], R[7]);
    R[1] = swp(R[1]); R[3] = swp(R[3]); R[5] = swp(R[5]); R[7] = swp(R[7]);

    pryR<4>(R, sc2[0][1][0], ss2[0][1][0], sn2[0][1][0]);
    pryR<2>(R, sc2[0][1][1], ss2[0][1][1], sn2[0][1][1]);
    pryR<1>(R, sc2[0][1][2], ss2[0][1][2], sn2[0][1][2]);
    {
        u64 c2 = sc2[0][1][3], mx = smix[1];
#pragma unroll
        for (int k = 0; k < 8; k++) R[k] = fma2(c2, R[k], mul2(mx, swp(R[k])));
    }
    // cnot 1->0, 2->1, 3->2
    sw2(R[2], R[6]); sw2(R[3], R[7]);
    sw2(R[1], R[3]); sw2(R[5], R[7]);
    hix(R[0], R[1]); hix(R[2], R[3]); hix(R[4], R[5]); hix(R[6], R[7]);

    // ---- layer-0 RZ: real -> complex packed (ar, ai) ----
    u64 P[16];
#pragma unroll
    for (int k = 0; k < 8; k++) {
        float ae, ao; upk(ae, ao, R[k]);
        P[2 * k]     = mul2(pk(ae, ae), sPz[2 * k]);
        P[2 * k + 1] = mul2(pk(ao, ao), sPz[2 * k + 1]);
    }

    // ---- layer 1 (complex packed; final RZ is pure phase -> skipped) ----
    pryP<8>(P, sc2[1][0][0], ss2[1][0][0], sn2[1][0][0]);
    pryP<4>(P, sc2[1][0][1], ss2[1][0][1], sn2[1][0][1]);
    pryP<2>(P, sc2[1][0][2], ss2[1][0][2], sn2[1][0][2]);
    pryP<1>(P, sc2[1][0][3], ss2[1][0][3], sn2[1][0][3]);
    cnotP<8, 4>(P); cnotP<4, 2>(P); cnotP<2, 1>(P);
    pryP<8>(P, sc2[1][1][0], ss2[1][1][0], sn2[1][1][0]);
    pryP<4>(P, sc2[1][1][1], ss2[1][1][1], sn2[1][1][1]);
    pryP<2>(P, sc2[1][1][2], ss2[1][1][2], sn2[1][1][2]);
    pryP<1>(P, sc2[1][1][3], ss2[1][1][3], sn2[1][1][3]);
    cnotP<4, 8>(P); cnotP<2, 4>(P); cnotP<1, 2>(P);

    // ---- probabilities and Z expectations ----
    float z0 = 0.f, z1 = 0.f, z2 = 0.f, z3 = 0.f;
#pragma unroll
    for (int idx = 0; idx < 16; idx++) {
        float pr, pi; upk(pr, pi, P[idx]);
        float pv = fmaf(pr, pr, pi * pi);
        z0 += (idx & 8) ? -pv : pv;
        z1 += (idx & 4) ? -pv : pv;
        z2 += (idx & 2) ? -pv : pv;
        z3 += (idx & 1) ? -pv : pv;
    }

    *reinterpret_cast<float4*>(out + b * 784 + p * 4) = make_float4(z0, z1, z2, z3);
}

// ---------------------------------------------------------------------------
extern "C" void kernel_launch(void* const* d_in, const int* in_sizes, int n_in,
                              void* d_out, int out_size) {
    const float* x = (const float*)d_in[0];
    const float* params = (const float*)d_in[1];
    if (n_in >= 2 && in_sizes[0] == 24) {   // robustness vs input ordering
        x = (const float*)d_in[1];
        params = (const float*)d_in[0];
    }
    float* out = (float*)d_out;

    qf_fused_kernel<<<NUM_P, 512>>>(x, params, out);
}

// round 6
// speedup vs baseline: 1.0582x; 1.0212x over previous
#include <cuda_runtime.h>
#include <cuda_bf16.h>

#define NUM_B 512
#define NUM_P 196          // 14*14 patch locations

typedef unsigned long long u64;

// ---------------------------------------------------------------------------
// f32x2 packed helpers (sm_103a packed fp32 pipe)
// ---------------------------------------------------------------------------
__device__ __forceinline__ u64 pk(float lo, float hi) {
    u64 r; asm("mov.b64 %0, {%1, %2};" : "=l"(r) : "f"(lo), "f"(hi)); return r;
}
__device__ __forceinline__ void upk(float& lo, float& hi, u64 v) {
    asm("mov.b64 {%0, %1}, %2;" : "=f"(lo), "=f"(hi) : "l"(v));
}
__device__ __forceinline__ u64 mul2(u64 a, u64 b) {
    u64 d; asm("mul.rn.f32x2 %0, %1, %2;" : "=l"(d) : "l"(a), "l"(b)); return d;
}
__device__ __forceinline__ u64 fma2(u64 a, u64 b, u64 c) {
    u64 d; asm("fma.rn.f32x2 %0, %1, %2, %3;" : "=l"(d) : "l"(a), "l"(b), "l"(c)); return d;
}
__device__ __forceinline__ u64 swp(u64 v) { float l, h; upk(l, h, v); return pk(h, l); }
__device__ __forceinline__ void sw2(u64& A, u64& B) { u64 t = A; A = B; B = t; }
// exchange hi lanes of A and B
__device__ __forceinline__ void hix(u64& A, u64& B) {
    float al, ah, bl, bh; upk(al, ah, A); upk(bl, bh, B);
    A = pk(al, bh); B = pk(bl, ah);
}
// packed RY on a pack pair: A' = c*A - s*B ; B' = s*A + c*B
__device__ __forceinline__ void pry(u64& A, u64& B, u64 c2, u64 s2, u64 n2) {
    u64 nA = fma2(n2, B, mul2(c2, A));
    u64 nB = fma2(s2, A, mul2(c2, B));
    A = nA; B = nB;
}

// real state: 8 packs, lane = wire3 bit; pack-index bits {4,2,1} = wires {0,1,2}
template <int M>
__device__ __forceinline__ void pryR(u64* R, u64 c2, u64 s2, u64 n2) {
#pragma unroll
    for (int k = 0; k < 8; k++)
        if (!(k & M)) pry(R[k], R[k | M], c2, s2, n2);
}
// complex state: 16 packs (ar, ai); idx bits {8,4,2,1} = wires {0,1,2,3}
template <int M>
__device__ __forceinline__ void pryP(u64* P, u64 c2, u64 s2, u64 n2) {
#pragma unroll
    for (int i = 0; i < 16; i++)
        if (!(i & M)) pry(P[i], P[i | M], c2, s2, n2);
}
template <int MC, int MT>
__device__ __forceinline__ void cnotP(u64* P) {
#pragma unroll
    for (int i = 0; i < 16; i++)
        if ((i & MC) && !(i & MT)) sw2(P[i], P[i | MT]);
}

// ---------------------------------------------------------------------------
// Fused kernel, balanced grid: 392 blocks x 256 threads.
// block = (patch location p, batch half). Stats computed redundantly per block
// (each thread loads rows tid and tid+256), then 256 circuits per block.
// ---------------------------------------------------------------------------
__global__ void __launch_bounds__(256)
qf_fused_kernel(const float* __restrict__ x,
                const float* __restrict__ params,
                float* __restrict__ out) {
    __shared__ float sh_s[8], sh_q[8];
    __shared__ float s_stats[2];                  // mean, pi/(std+eps)
    __shared__ u64 sc2[2][2][4], ss2[2][2][4], sn2[2][2][4]; // dup'd cos/sin/-sin
    __shared__ u64 smix[2];                       // layer0 wire3 in-lane (-s,+s)
    __shared__ u64 sPz[16];                       // layer-0 RZ phasor packs

    const int p    = blockIdx.x >> 1;
    const int half = blockIdx.x & 1;
    const int r = p / 14, c = p % 14;
    const int tid = threadIdx.x;
    const int lane = tid & 31, wid = tid >> 5;

    // --- load two samples' 2x2 patches (rows tid and tid+256) ---
    const float* x0 = x + tid * 784 + (2 * r) * 28 + 2 * c;
    const float* x1 = x0 + 256 * 784;
    float w0 = x0[0], w1 = x0[1], w2 = x0[28], w3 = x0[29];
    float y0 = x1[0], y1 = x1[1], y2 = x1[28], y3 = x1[29];

    // --- Phase A: stats over all 512 samples (2048 values) ---
    float s = ((w0 + w1) + (w2 + w3)) + ((y0 + y1) + (y2 + y3));
    float q = (w0 * w0 + w1 * w1 + w2 * w2 + w3 * w3)
            + (y0 * y0 + y1 * y1 + y2 * y2 + y3 * y3);
#pragma unroll
    for (int o = 16; o > 0; o >>= 1) {
        s += __shfl_down_sync(0xffffffffu, s, o);
        q += __shfl_down_sync(0xffffffffu, q, o);
    }
    if (lane == 0) { sh_s[wid] = s; sh_q[wid] = q; }

    // params-only precompute on thread 32 (overlaps the reduction tail)
    if (tid == 32) {
        float cz[4], sz[4];
#pragma unroll
        for (int l = 0; l < 2; l++)
#pragma unroll
            for (int i = 0; i < 4; i++) {
                float s_, c_;
                __sincosf(0.5f * params[l * 12 + i * 3 + 0], &s_, &c_);
                sc2[l][0][i] = pk(c_, c_); ss2[l][0][i] = pk(s_, s_); sn2[l][0][i] = pk(-s_, -s_);
                if (l == 0 && i == 3) smix[0] = pk(-s_, s_);
                __sincosf(0.5f * params[l * 12 + i * 3 + 1], &s_, &c_);
                sc2[l][1][i] = pk(c_, c_); ss2[l][1][i] = pk(s_, s_); sn2[l][1][i] = pk(-s_, -s_);
                if (l == 0 && i == 3) smix[1] = pk(-s_, s_);
            }
#pragma unroll
        for (int i = 0; i < 4; i++)
            __sincosf(0.5f * params[i * 3 + 2], &sz[i], &cz[i]);
#pragma unroll
        for (int idx = 0; idx < 16; idx++) {
            float pr = 1.f, pim = 0.f;
#pragma unroll
            for (int w = 0; w < 4; w++) {
                float swv = (idx & (8 >> w)) ? sz[w] : -sz[w];
                float nr = pr * cz[w] - pim * swv;
                pim = pr * swv + pim * cz[w];
                pr = nr;
            }
            sPz[idx] = pk(pr, pim);
        }
    }
    __syncthreads();
    if (tid < 32) {
        float fs = (lane < 8) ? sh_s[lane] : 0.f;
        float fq = (lane < 8) ? sh_q[lane] : 0.f;
#pragma unroll
        for (int o = 4; o > 0; o >>= 1) {
            fs += __shfl_down_sync(0xffffffffu, fs, o);
            fq += __shfl_down_sync(0xffffffffu, fq, o);
        }
        if (lane == 0) {
            const float n = 2048.0f;
            float mean = fs / n;
            float var = fmaxf((fq - fs * mean) / (n - 1.0f), 0.0f);
            s_stats[0] = mean;
            s_stats[1] = 3.14159265358979323846f / (sqrtf(var) + 1e-8f);
        }
    }
    __syncthreads();

    // --- Phase B: circuit for sample b = half*256 + tid ---
    float v0 = half ? y0 : w0, v1 = half ? y1 : w1;
    float v2 = half ? y2 : w2, v3 = half ? y3 : w3;
    const float m = s_stats[0], inv = s_stats[1];
    float cw[4], sw[4];
    __sincosf(0.5f * (v0 - m) * inv, &sw[0], &cw[0]);
    __sincosf(0.5f * (v1 - m) * inv, &sw[1], &cw[1]);
    __sincosf(0.5f * (v2 - m) * inv, &sw[2], &cw[2]);
    __sincosf(0.5f * (v3 - m) * inv, &sw[3], &cw[3]);

    // initial product state after input RYs (real), packed along wire3
    u64 R[8];
    {
        u64 g3 = pk(cw[3], sw[3]);
#pragma unroll
        for (int k = 0; k < 8; k++) {
            float f = ((k & 4) ? sw[0] : cw[0]) * ((k & 2) ? sw[1] : cw[1])
                    * ((k & 1) ? sw[2] : cw[2]);
            R[k] = mul2(pk(f, f), g3);
        }
    }

    // ---- layer 0 (real) ----
    pryR<4>(R, sc2[0][0][0], ss2[0][0][0], sn2[0][0][0]);   // wire0
    pryR<2>(R, sc2[0][0][1], ss2[0][0][1], sn2[0][0][1]);   // wire1
    pryR<1>(R, sc2[0][0][2], ss2[0][0][2], sn2[0][0][2]);   // wire2
    {   // wire3 (lane bit): in-lane packed RY
        u64 c2 = sc2[0][0][3], mx = smix[0];
#pragma unroll
        for (int k = 0; k < 8; k++) R[k] = fma2(c2, R[k], mul2(mx, swp(R[k])));
    }
    // cnot 0->1, 1->2, 2->3
    sw2(R[4], R[6]); sw2(R[5], R[7]);
    sw2(R[2], R[3]); sw2(R[6], R[7]);
    R[1] = swp(R[1]); R[3] = swp(R[3]); R[5] = swp(R[5]); R[7] = swp(R[7]);

    pryR<4>(R, sc2[0][1][0], ss2[0][1][0], sn2[0][1][0]);
    pryR<2>(R, sc2[0][1][1], ss2[0][1][1], sn2[0][1][1]);
    pryR<1>(R, sc2[0][1][2], ss2[0][1][2], sn2[0][1][2]);
    {
        u64 c2 = sc2[0][1][3], mx = smix[1];
#pragma unroll
        for (int k = 0; k < 8; k++) R[k] = fma2(c2, R[k], mul2(mx, swp(R[k])));
    }
    // cnot 1->0, 2->1, 3->2
    sw2(R[2], R[6]); sw2(R[3], R[7]);
    sw2(R[1], R[3]); sw2(R[5], R[7]);
    hix(R[0], R[1]); hix(R[2], R[3]); hix(R[4], R[5]); hix(R[6], R[7]);

    // ---- layer-0 RZ: real -> complex packed (ar, ai) ----
    u64 P[16];
#pragma unroll
    for (int k = 0; k < 8; k++) {
        float ae, ao; upk(ae, ao, R[k]);
        P[2 * k]     = mul2(pk(ae, ae), sPz[2 * k]);
        P[2 * k + 1] = mul2(pk(ao, ao), sPz[2 * k + 1]);
    }

    // ---- layer 1 (complex packed; final RZ is pure phase -> skipped) ----
    pryP<8>(P, sc2[1][0][0], ss2[1][0][0], sn2[1][0][0]);
    pryP<4>(P, sc2[1][0][1], ss2[1][0][1], sn2[1][0][1]);
    pryP<2>(P, sc2[1][0][2], ss2[1][0][2], sn2[1][0][2]);
    pryP<1>(P, sc2[1][0][3], ss2[1][0][3], sn2[1][0][3]);
    cnotP<8, 4>(P); cnotP<4, 2>(P); cnotP<2, 1>(P);
    pryP<8>(P, sc2[1][1][0], ss2[1][1][0], sn2[1][1][0]);
    pryP<4>(P, sc2[1][1][1], ss2[1][1][1], sn2[1][1][1]);
    pryP<2>(P, sc2[1][1][2], ss2[1][1][2], sn2[1][1][2]);
    pryP<1>(P, sc2[1][1][3], ss2[1][1][3], sn2[1][1][3]);
    cnotP<4, 8>(P); cnotP<2, 4>(P); cnotP<1, 2>(P);

    // ---- probabilities ----
    float pv[16];
#pragma unroll
    for (int idx = 0; idx < 16; idx++) {
        float pr, pi; upk(pr, pi, P[idx]);
        pv[idx] = fmaf(pr, pr, pi * pi);
    }
    // ---- Z expectations via Walsh-Hadamard tree ----
    // idx bit3 -> z0, bit2 -> z1, bit1 -> z2, bit0 -> z3
    float a[8], d[8];
#pragma unroll
    for (int k = 0; k < 8; k++) { a[k] = pv[2*k] + pv[2*k+1]; d[k] = pv[2*k] - pv[2*k+1]; }
    float z3 = ((d[0] + d[1]) + (d[2] + d[3])) + ((d[4] + d[5]) + (d[6] + d[7]));
    float b4[4], e4[4];
#pragma unroll
    for (int j = 0; j < 4; j++) { b4[j] = a[2*j] + a[2*j+1]; e4[j] = a[2*j] - a[2*j+1]; }
    float z2 = (e4[0] + e4[1]) + (e4[2] + e4[3]);
    float c0 = b4[0] + b4[1], c1 = b4[2] + b4[3];
    float z1 = (b4[0] - b4[1]) + (b4[2] - b4[3]);
    float z0 = c0 - c1;

    const int b_out = half * 256 + tid;
    *reinterpret_cast<float4*>(out + b_out * 784 + p * 4) = make_float4(z0, z1, z2, z3);
}

// ---------------------------------------------------------------------------
extern "C" void kernel_launch(void* const* d_in, const int* in_sizes, int n_in,
                              void* d_out, int out_size) {
    const float* x = (const float*)d_in[0];
    const float* params = (const float*)d_in[1];
    if (n_in >= 2 && in_sizes[0] == 24) {   // robustness vs input ordering
        x = (const float*)d_in[1];
        params = (const float*)d_in[0];
    }
    float* out = (float*)d_out;

    qf_fused_kernel<<<2 * NUM_P, 256>>>(x, params, out);
}

// round 8
// speedup vs baseline: 1.1976x; 1.1317x over previous
#include <cuda_runtime.h>
#include <cuda_bf16.h>

#define NUM_B 512
#define NUM_P 196          // 14*14 patch locations

// ---------------------------------------------------------------------------
// Scalar gate helpers (16 amplitudes in registers, fully unrolled).
// amplitude index bits: 8=wire0, 4=wire1, 2=wire2, 1=wire3
// ---------------------------------------------------------------------------
template <int M>
__device__ __forceinline__ void ry_real(float* a, float c, float s) {
#pragma unroll
    for (int i = 0; i < 16; i++)
        if (!(i & M)) {
            const int j = i | M;
            float a0 = a[i], a1 = a[j];
            a[i] = c * a0 - s * a1;   // FFMA with negated operand (free)
            a[j] = s * a0 + c * a1;
        }
}

template <int M>
__device__ __forceinline__ void ry_cplx(float* ar, float* ai, float c, float s) {
#pragma unroll
    for (int i = 0; i < 16; i++)
        if (!(i & M)) {
            const int j = i | M;
            float r0 = ar[i], r1 = ar[j];
            ar[i] = c * r0 - s * r1;
            ar[j] = s * r0 + c * r1;
            float i0 = ai[i], i1 = ai[j];
            ai[i] = c * i0 - s * i1;
            ai[j] = s * i0 + c * i1;
        }
}

template <int MC, int MT>
__device__ __forceinline__ void cnot_real(float* a) {
#pragma unroll
    for (int i = 0; i < 16; i++)
        if ((i & MC) && !(i & MT)) {
            const int j = i | MT;
            float t = a[i]; a[i] = a[j]; a[j] = t;   // register rename, free
        }
}

template <int MC, int MT>
__device__ __forceinline__ void cnot_cplx(float* ar, float* ai) {
    cnot_real<MC, MT>(ar);
    cnot_real<MC, MT>(ai);
}

// ---------------------------------------------------------------------------
// Fused kernel: 392 blocks x 256 threads. block = (patch p, batch half).
// Phase A: redundant per-block stats over all 512 samples.
// Phase B: one circuit per thread (sample = half*256 + tid).
// ---------------------------------------------------------------------------
__global__ void __launch_bounds__(256)
qf_fused_kernel(const float* __restrict__ x,
                const float* __restrict__ params,
                float* __restrict__ out) {
    __shared__ float sh_s[8], sh_q[8];
    __shared__ float s_stats[2];          // mean, pi/(std+eps)
    __shared__ float sP0[4];              // params[0][w][0] (merged into input RY)
    __shared__ float sC[3][4], sS[3][4];  // cos/sin half-angle: l0col1, l1col0, l1col1
    __shared__ float sPr[16], sPi[16];    // layer-0 RZ phasors

    const int p    = blockIdx.x >> 1;
    const int half = blockIdx.x & 1;
    const int r = p / 14, c = p % 14;
    const int tid = threadIdx.x;
    const int lane = tid & 31, wid = tid >> 5;

    // --- load two samples' 2x2 patches (rows tid and tid+256) ---
    const float* x0 = x + tid * 784 + (2 * r) * 28 + 2 * c;
    const float* x1 = x0 + 256 * 784;
    float w0 = x0[0], w1 = x0[1], w2 = x0[28], w3 = x0[29];
    float y0 = x1[0], y1 = x1[1], y2 = x1[28], y3 = x1[29];

    // --- Phase A: stats over 2048 values ---
    float s = ((w0 + w1) + (w2 + w3)) + ((y0 + y1) + (y2 + y3));
    float q = (w0 * w0 + w1 * w1 + w2 * w2 + w3 * w3)
            + (y0 * y0 + y1 * y1 + y2 * y2 + y3 * y3);
#pragma unroll
    for (int o = 16; o > 0; o >>= 1) {
        s += __shfl_down_sync(0xffffffffu, s, o);
        q += __shfl_down_sync(0xffffffffu, q, o);
    }
    if (lane == 0) { sh_s[wid] = s; sh_q[wid] = q; }

    // params-only precompute on thread 32 (overlaps the reduction tail)
    if (tid == 32) {
        float cz[4], sz[4];
#pragma unroll
        for (int i = 0; i < 4; i++) {
            sP0[i] = params[i * 3 + 0];                       // merged RY col
            float s_, c_;
            __sincosf(0.5f * params[i * 3 + 1], &s_, &c_);    // l0 col1
            sC[0][i] = c_; sS[0][i] = s_;
            __sincosf(0.5f * params[12 + i * 3 + 0], &s_, &c_); // l1 col0
            sC[1][i] = c_; sS[1][i] = s_;
            __sincosf(0.5f * params[12 + i * 3 + 1], &s_, &c_); // l1 col1
            sC[2][i] = c_; sS[2][i] = s_;
            __sincosf(0.5f * params[i * 3 + 2], &sz[i], &cz[i]); // l0 RZ
        }
#pragma unroll
        for (int idx = 0; idx < 16; idx++) {
            float pr = 1.f, pim = 0.f;
#pragma unroll
            for (int w = 0; w < 4; w++) {
                float swv = (idx & (8 >> w)) ? sz[w] : -sz[w];
                float nr = pr * cz[w] - pim * swv;
                pim = pr * swv + pim * cz[w];
                pr = nr;
            }
            sPr[idx] = pr; sPi[idx] = pim;
        }
    }
    __syncthreads();
    if (tid < 32) {
        float fs = (lane < 8) ? sh_s[lane] : 0.f;
        float fq = (lane < 8) ? sh_q[lane] : 0.f;
#pragma unroll
        for (int o = 4; o > 0; o >>= 1) {
            fs += __shfl_down_sync(0xffffffffu, fs, o);
            fq += __shfl_down_sync(0xffffffffu, fq, o);
        }
        if (lane == 0) {
            const float n = 2048.0f;
            float mean = fs / n;
            float var = fmaxf((fq - fs * mean) / (n - 1.0f), 0.0f);
            s_stats[0] = mean;
            s_stats[1] = 3.14159265358979323846f / (sqrtf(var) + 1e-8f);
        }
    }
    __syncthreads();

    // --- Phase B: circuit ---
    float v0 = half ? y0 : w0, v1 = half ? y1 : w1;
    float v2 = half ? y2 : w2, v3 = half ? y3 : w3;
    const float m = s_stats[0], inv = s_stats[1];

    // input RY merged with layer-0 first RY column: theta_w = norm + params[0][w][0]
    float cw[4], sw[4];
    __sincosf(0.5f * ((v0 - m) * inv + sP0[0]), &sw[0], &cw[0]);
    __sincosf(0.5f * ((v1 - m) * inv + sP0[1]), &sw[1], &cw[1]);
    __sincosf(0.5f * ((v2 - m) * inv + sP0[2]), &sw[2], &cw[2]);
    __sincosf(0.5f * ((v3 - m) * inv + sP0[3]), &sw[3], &cw[3]);

    // product state (real)
    float ar[16], ai[16];
    {
        float f01[4] = { cw[0] * cw[1], cw[0] * sw[1], sw[0] * cw[1], sw[0] * sw[1] };
        float f23[4] = { cw[2] * cw[3], cw[2] * sw[3], sw[2] * cw[3], sw[2] * sw[3] };
#pragma unroll
        for (int hi = 0; hi < 4; hi++)
#pragma unroll
            for (int lo = 0; lo < 4; lo++)
                ar[hi * 4 + lo] = f01[hi] * f23[lo];
    }

    // ---- layer 0 remainder (real) ----
    cnot_real<8, 4>(ar); cnot_real<4, 2>(ar); cnot_real<2, 1>(ar);
    ry_real<8>(ar, sC[0][0], sS[0][0]);
    ry_real<4>(ar, sC[0][1], sS[0][1]);
    ry_real<2>(ar, sC[0][2], sS[0][2]);
    ry_real<1>(ar, sC[0][3], sS[0][3]);
    cnot_real<4, 8>(ar); cnot_real<2, 4>(ar); cnot_real<1, 2>(ar);
    // RZ: real -> complex via precomputed phasors
#pragma unroll
    for (int idx = 0; idx < 16; idx++) {
        ai[idx] = ar[idx] * sPi[idx];
        ar[idx] = ar[idx] * sPr[idx];
    }

    // ---- layer 1 (complex; final RZ is pure phase -> skipped) ----
    ry_cplx<8>(ar, ai, sC[1][0], sS[1][0]);
    ry_cplx<4>(ar, ai, sC[1][1], sS[1][1]);
    ry_cplx<2>(ar, ai, sC[1][2], sS[1][2]);
    ry_cplx<1>(ar, ai, sC[1][3], sS[1][3]);
    cnot_cplx<8, 4>(ar, ai); cnot_cplx<4, 2>(ar, ai); cnot_cplx<2, 1>(ar, ai);
    ry_cplx<8>(ar, ai, sC[2][0], sS[2][0]);
    ry_cplx<4>(ar, ai, sC[2][1], sS[2][1]);
    ry_cplx<2>(ar, ai, sC[2][2], sS[2][2]);
    ry_cplx<1>(ar, ai, sC[2][3], sS[2][3]);
    cnot_cplx<4, 8>(ar, ai); cnot_cplx<2, 4>(ar, ai); cnot_cplx<1, 2>(ar, ai);

    // ---- probabilities ----
    float pv[16];
#pragma unroll
    for (int idx = 0; idx < 16; idx++)
        pv[idx] = fmaf(ar[idx], ar[idx], ai[idx] * ai[idx]);

    // ---- Z expectations via Walsh-Hadamard tree ----
    float a8[8], d8[8];
#pragma unroll
    for (int k = 0; k < 8; k++) { a8[k] = pv[2*k] + pv[2*k+1]; d8[k] = pv[2*k] - pv[2*k+1]; }
    float z3 = ((d8[0] + d8[1]) + (d8[2] + d8[3])) + ((d8[4] + d8[5]) + (d8[6] + d8[7]));
    float b4[4], e4[4];
#pragma unroll
    for (int j = 0; j < 4; j++) { b4[j] = a8[2*j] + a8[2*j+1]; e4[j] = a8[2*j] - a8[2*j+1]; }
    float z2 = (e4[0] + e4[1]) + (e4[2] + e4[3]);
    float z1 = (b4[0] - b4[1]) + (b4[2] - b4[3]);
    float z0 = (b4[0] + b4[1]) - (b4[2] + b4[3]);

    const int b_out = half * 256 + tid;
    *reinterpret_cast<float4*>(out + b_out * 784 + p * 4) = make_float4(z0, z1, z2, z3);
}

// ---------------------------------------------------------------------------
extern "C" void kernel_launch(void* const* d_in, const int* in_sizes, int n_in,
                              void* d_out, int out_size) {
    const float* x = (const float*)d_in[0];
    const float* params = (const float*)d_in[1];
    if (n_in >= 2 && in_sizes[0] == 24) {   // robustness vs input ordering
        x = (const float*)d_in[1];
        params = (const float*)d_in[0];
    }
    float* out = (float*)d_out;

    qf_fused_kernel<<<2 * NUM_P, 256>>>(x, params, out);
}